// round 6
// baseline (speedup 1.0000x reference)
#include <cuda_runtime.h>

namespace {

constexpr int T_ = 128, H_ = 16, N_ = 64, C_ = 256, S_ = 129;
constexpr int NW   = 31;    // producer warps; warp 31 = consumer
constexpr int RING = 32;    // G-row ring depth

constexpr float L2E     = 1.4426950408889634f;
constexpr float LN2     = 0.6931471805599453f;
constexpr float MINF    = 1.17549435e-38f;       // 2^-126 == FLT_MIN == TINY
constexpr float NEG_BIG = -1e30f;

__device__ __forceinline__ float ex2f(float x) { float y; asm("ex2.approx.f32 %0, %1;" : "=f"(y) : "f"(x)); return y; }
__device__ __forceinline__ float lg2f(float x) { float y; asm("lg2.approx.f32 %0, %1;" : "=f"(y) : "f"(x)); return y; }

__global__ __launch_bounds__(1024, 1) void fused_kernel(
    const float* __restrict__ mask,      // [T,H,N]
    const float* __restrict__ classify,  // [T,H,N,C]
    const int*   __restrict__ targets,   // [N,64]
    const int*   __restrict__ tlen,      // [N]
    float* __restrict__ out)             // [N]
{
    __shared__ float        ring[RING][68];     // G2 rows (log2 domain)
    __shared__ float        rowbuf[NW][256];    // per-producer-warp row transpose buffer
    __shared__ volatile int flag[T_];           // row-ready flags
    __shared__ volatile int prog;               // consumer progress (last row consumed)
    __shared__ int          tgt_sh[64];
    __shared__ int          cc_sh[T_];
    __shared__ float        res_sh[S_];

    const int n    = blockIdx.x;
    const int tid  = threadIdx.x;
    const int w    = tid >> 5;
    const int lane = tid & 31;

    if (tid < T_) flag[tid] = 0;
    if (tid == 0) prog = -1;
    if (tid < 64) tgt_sh[tid] = targets[n * 64 + tid];
    __syncthreads();

    if (w < NW) {
        // ======================= producer warp =======================
        // flat row sequence j: row j -> (t = w + 31*(j>>4), h = j&15)
        const int col1 = (lane == 0) ? 0 : tgt_sh[lane - 1];   // cols 0..31
        const int col2 = tgt_sh[31 + lane];                     // cols 32..63
        const int col3 = tgt_sh[63];                            // col 64
        const int nt   = (w < 4) ? 5 : 4;                       // 31*4+4 = 128
        const int jmax = nt * 16;
        float* rb = &rowbuf[w][0];

        // per-row register staging, 4 deep
        float4 a[4], b[4];
#pragma unroll
        for (int jj = 0; jj < 4; ++jj) {   // prologue: rows (t=w, h=0..3)
            const float* base = classify + (((size_t)w * H_ + jj) * N_ + n) * C_;
            a[jj] = *reinterpret_cast<const float4*>(base + 4 * lane);
            b[jj] = *reinterpret_cast<const float4*>(base + 128 + 4 * lane);
        }
        float mcur = (lane < 16) ? __ldg(&mask[((size_t)w * H_ + lane) * N_ + n]) : 0.f;
        float mnext = 0.f;

        float s1 = 0.f, s2 = 0.f, s3 = 0.f;

        for (int j = 0; j < jmax; ++j) {
            const int slot = j & 3;
            const int h    = j & 15;
            const int t    = w + 31 * (j >> 4);

            // stage row j into rowbuf
            *reinterpret_cast<float4*>(rb + 4 * lane)       = a[slot];
            *reinterpret_cast<float4*>(rb + 128 + 4 * lane) = b[slot];

            // issue load of row j+4 into the freed slot
            if (j + 4 < jmax) {
                const int t4 = w + 31 * ((j + 4) >> 4);
                const int h4 = (j + 4) & 15;
                const float* base = classify + (((size_t)t4 * H_ + h4) * N_ + n) * C_;
                a[slot] = *reinterpret_cast<const float4*>(base + 4 * lane);
                b[slot] = *reinterpret_cast<const float4*>(base + 128 + 4 * lane);
            }
            // prefetch next t's mask early in the t window
            if (h == 0 && j + 16 < jmax && lane < 16)
                mnext = __ldg(&mask[(((size_t)t + 31) * H_ + lane) * N_ + n]);

            __syncwarp();   // STS visible to all lanes

            const float mh = __shfl_sync(0xffffffffu, mcur, h) * L2E;
            const float v1 = rb[col1];
            const float v2 = rb[col2];
            const float v3 = rb[col3];
            s1 += ex2f(__fmaf_rn(v1, L2E, mh));
            s2 += ex2f(__fmaf_rn(v2, L2E, mh));
            s3 += ex2f(__fmaf_rn(v3, L2E, mh));

            __syncwarp();   // all LDS done before next overwrite

            if (h == 15) {
                const float g1 = lg2f(s1), g2 = lg2f(s2), g3 = lg2f(s3);
                if (t >= RING) { while (prog < t - RING) {} }   // ring backpressure
                float* gr = &ring[t & (RING - 1)][0];
                gr[lane]      = g1;
                gr[32 + lane] = g2;
                if (lane == 31) gr[64] = g3;
                __syncwarp();
                __threadfence_block();
                if (lane == 0) flag[t] = 1;
                s1 = s2 = s3 = 0.f;
                mcur = mnext;
            }
        }
        return;
    }

    // ======================= consumer warp (w == 31) =======================
    const int NS = (lane == 31) ? 5 : 4;
    const int sB = 4 * lane;

    // cc prefix scan (reachability frontier)
    {
        int c[4], pfx = 0;
#pragma unroll
        for (int i = 0; i < 4; ++i) {
            int u = 4 * lane + i, v = 0;
            if (u >= 2) {
                int sk = 0;
                if ((u & 1) && u >= 3) sk = (tgt_sh[(u - 1) >> 1] != tgt_sh[(u - 3) >> 1]);
                v = sk + 1;
            }
            pfx += v; c[i] = pfx;
        }
        int tot = pfx;
#pragma unroll
        for (int d = 1; d < 32; d <<= 1) {
            int up = __shfl_up_sync(0xffffffffu, tot, d);
            if (lane >= d) tot += up;
        }
        int excl = tot - pfx;
#pragma unroll
        for (int i = 0; i < 4; ++i) {
            int u = 4 * lane + i;
            if (u >= 1) cc_sh[u] = 2 + excl + c[i];
        }
    }
    __syncwarp();

    bool skipb[5];
#pragma unroll
    for (int i = 0; i < 5; ++i) {
        int s = sB + i;
        skipb[i] = (i < NS) && (s & 1) && (s >= 3) &&
                   (tgt_sh[(s - 1) >> 1] != tgt_sh[(s - 3) >> 1]);
    }

    const int cO1 = 2 * lane + 1;   // ring col of state 4l+1
    const int cO2 = 2 * lane + 2;   // ring col of state 4l+3

    float np[5];
#pragma unroll
    for (int i = 0; i < 5; ++i) np[i] = (sB + i < 2) ? 0.f : NEG_BIG;

    // row 0
    while (flag[0] == 0) {}
    __threadfence_block();
    float gE = ring[0][0], gO1 = ring[0][cO1], gO2 = ring[0][cO2];
    __syncwarp();
    if (lane == 0) prog = 0;

    for (int t = 1; t < T_; ++t) {
        while (flag[t] == 0) {}
        __threadfence_block();
        const float* r = &ring[t & (RING - 1)][0];
        const float aE = r[0], aO1 = r[cO1], aO2 = r[cO2];
        __syncwarp();                   // reads done before releasing the slot
        if (lane == 0) prog = t;

        const int cc_t = cc_sh[t];

        // E-domain step: E = max(ex2(np+g), 2^-126)  [== reference's TINY clamp]
        float e[5];
        e[0] = fmaxf(ex2f(np[0] + gE),  MINF);
        e[1] = fmaxf(ex2f(np[1] + gO1), MINF);
        e[2] = fmaxf(ex2f(np[2] + gE),  MINF);
        e[3] = fmaxf(ex2f(np[3] + gO2), MINF);
        e[4] = fmaxf(ex2f(np[4] + gE),  MINF);
#pragma unroll
        for (int i = 0; i < 5; ++i)
            if (sB + i > cc_t) e[i] = MINF;

        const float em1 = __shfl_up_sync(0xffffffffu, e[3], 1);
        const float em2 = __shfl_up_sync(0xffffffffu, e[2], 1);

        np[0] = (lane == 0) ? lg2f(e[0])
                            : lg2f(e[0] + em1 + (skipb[0] ? em2 : 0.f));
        np[1] = lg2f(e[1] + e[0] + (skipb[1] ? em1 : 0.f));
#pragma unroll
        for (int i = 2; i < 5; ++i)
            np[i] = lg2f(e[i] + e[i - 1] + (skipb[i] ? e[i - 2] : 0.f));

        gE = aE; gO1 = aO1; gO2 = aO2;
    }

    // final: res2[s] = np2[s] + G2[127][s]
    res_sh[sB + 0] = np[0] + gE;
    res_sh[sB + 1] = np[1] + gO1;
    res_sh[sB + 2] = np[2] + gE;
    res_sh[sB + 3] = np[3] + gO2;
    if (lane == 31) res_sh[128] = np[4] + gE;
    __syncwarp();

    if (lane == 0) {
        const int   L = 2 * tlen[n] + 1;
        const float x = res_sh[L - 1], y = res_sh[L - 2];
        const float m = fmaxf(x, y);
        const float l2 = m + lg2f(ex2f(x - m) + ex2f(y - m));
        out[n] = -((LN2 * l2) / (float)tlen[n]);
    }
}

} // anonymous namespace

extern "C" void kernel_launch(void* const* d_in, const int* /*in_sizes*/, int /*n_in*/,
                              void* d_out, int /*out_size*/) {
    const float* mask     = (const float*)d_in[0];
    const float* classify = (const float*)d_in[1];
    const int*   targets  = (const int*)d_in[2];
    // d_in[3] = input_lengths (always T, unused)
    const int*   tlen     = (const int*)d_in[4];

    fused_kernel<<<N_, 1024>>>(mask, classify, targets, tlen, (float*)d_out);
}

// round 7
// speedup vs baseline: 1.2146x; 1.2146x over previous
#include <cuda_runtime.h>
#include <cstdint>

namespace {

constexpr int T_ = 128, H_ = 16, N_ = 64, C_ = 256, S_ = 129;
constexpr int NC_ = N_ * C_;

constexpr float L2E     = 1.4426950408889634f;
constexpr float LN2     = 0.6931471805599453f;
constexpr float MINF    = 1.17549435e-38f;     // 2^-126 == FLT_MIN == TINY
constexpr float NEG_BIG = -1e30f;

__device__ __forceinline__ float ex2f(float x) { float y; asm("ex2.approx.f32 %0, %1;" : "=f"(y) : "f"(x)); return y; }
__device__ __forceinline__ float lg2f(float x) { float y; asm("lg2.approx.f32 %0, %1;" : "=f"(y) : "f"(x)); return y; }

__device__ __forceinline__ uint32_t smem_u32(const void* p) {
    uint32_t a;
    asm("{ .reg .u64 t; cvta.to.shared.u64 t, %1; cvt.u32.u64 %0, t; }" : "=r"(a) : "l"(p));
    return a;
}
__device__ __forceinline__ uint32_t mapa_rank0(uint32_t local) {
    uint32_t r;
    asm("mapa.shared::cluster.u32 %0, %1, 0;" : "=r"(r) : "r"(local));
    return r;
}
__device__ __forceinline__ void st_cl_f32(uint32_t a, float v) {
    asm volatile("st.shared::cluster.f32 [%0], %1;" :: "r"(a), "f"(v));
}
__device__ __forceinline__ void st_cl_u32(uint32_t a, unsigned v) {
    asm volatile("st.shared::cluster.u32 [%0], %1;" :: "r"(a), "r"(v));
}
__device__ __forceinline__ void fence_cluster() {
    asm volatile("fence.acq_rel.cluster;" ::: "memory");
}
__device__ __forceinline__ void cluster_sync() {
    asm volatile("barrier.cluster.arrive.aligned;" ::: "memory");
    asm volatile("barrier.cluster.wait.aligned;" ::: "memory");
}
__device__ __forceinline__ uint32_t ctarank() {
    uint32_t r; asm("mov.u32 %0, %%cluster_ctarank;" : "=r"(r)); return r;
}

// Cluster of 2 CTAs per batch item n. Rank0: 15 producer warps + consumer
// warp 15. Rank1: 16 producer warps. All producers write G2 rows (log2 domain,
// 65 deduped columns) into rank0's smem via DSMEM, release with cluster fence
// + flag. Consumer runs the serial CTC recurrence out of local smem.
__global__ __launch_bounds__(512, 1) __cluster_dims__(2, 1, 1)
void fused_kernel(
    const float* __restrict__ mask,      // [T,H,N]
    const float* __restrict__ classify,  // [T,H,N,C]
    const int*   __restrict__ targets,   // [N,64]
    const int*   __restrict__ tlen,      // [N]
    float* __restrict__ out)             // [N]
{
    __shared__ float        G_sh[T_][68];
    __shared__ volatile int flag[T_];
    __shared__ int          tgt_sh[64];
    __shared__ int          cc_sh[T_];
    __shared__ float        res_sh[S_];

    const int n    = blockIdx.x >> 1;
    const int rank = (int)ctarank();
    const int tid  = threadIdx.x;
    const int w    = tid >> 5;
    const int lane = tid & 31;

    if (rank == 0 && tid < T_) flag[tid] = 0;
    if (tid < 64) tgt_sh[tid] = targets[n * 64 + tid];
    __syncthreads();
    cluster_sync();                     // flags initialized before any producer release

    const bool isProd = (rank == 1) || (w < 15);

    if (isProd) {
        // ======================= producer warp =======================
        const int pid  = (rank == 0) ? w : (15 + w);   // 0..30
        const int col1 = (lane == 0) ? 0 : tgt_sh[lane - 1];   // cols 0..31
        const int col2 = tgt_sh[31 + lane];                    // cols 32..63
        const int col3 = tgt_sh[63];                           // col 64
        const size_t b1 = (size_t)n * C_ + col1;
        const size_t b2 = (size_t)n * C_ + col2;
        const size_t b3 = (size_t)n * C_ + col3;
        const bool   l31 = (lane == 31);

        for (int t = pid; t < T_; t += 31) {
            const float* base = classify + (size_t)t * H_ * NC_;
            const float  m = (lane < 16) ? __ldg(&mask[((size_t)t * H_ + lane) * N_ + n]) : 0.f;

            float v1[H_], v2[H_], v3[H_];
#pragma unroll
            for (int h = 0; h < H_; ++h) {
                const size_t ho = (size_t)h * NC_;
                v1[h] = __ldg(base + ho + b1);
                v2[h] = __ldg(base + ho + b2);
            }
            if (l31) {
#pragma unroll
                for (int h = 0; h < H_; ++h) v3[h] = __ldg(base + (size_t)h * NC_ + b3);
            }

            float s1 = 0.f, s2 = 0.f, s3 = 0.f;
#pragma unroll
            for (int h = 0; h < H_; ++h) {
                const float mh = __shfl_sync(0xffffffffu, m, h) * L2E;
                s1 += ex2f(__fmaf_rn(v1[h], L2E, mh));
                s2 += ex2f(__fmaf_rn(v2[h], L2E, mh));
                if (l31) s3 += ex2f(__fmaf_rn(v3[h], L2E, mh));
            }

            // write row t into rank0's smem (DSMEM for rank1; local for rank0)
            const uint32_t rloc = smem_u32(&G_sh[t][0]);
            const uint32_t r0   = mapa_rank0(rloc);
            st_cl_f32(r0 + 4u * lane,        lg2f(s1));
            st_cl_f32(r0 + 4u * (32 + lane), lg2f(s2));
            if (l31) st_cl_f32(r0 + 4u * 64, lg2f(s3));
            fence_cluster();                 // per-lane release of its stores
            __syncwarp();
            if (lane == 0) st_cl_u32(mapa_rank0(smem_u32((const void*)&flag[t])), 1u);
        }
        return;
    }

    // ======================= consumer warp (rank0, w == 15) =======================
    const int NS = (lane == 31) ? 5 : 4;
    const int sB = 4 * lane;

    // cc prefix scan (reachability frontier)
    {
        int c[4], pfx = 0;
#pragma unroll
        for (int i = 0; i < 4; ++i) {
            int u = 4 * lane + i, v = 0;
            if (u >= 2) {
                int sk = 0;
                if ((u & 1) && u >= 3) sk = (tgt_sh[(u - 1) >> 1] != tgt_sh[(u - 3) >> 1]);
                v = sk + 1;
            }
            pfx += v; c[i] = pfx;
        }
        int tot = pfx;
#pragma unroll
        for (int d = 1; d < 32; d <<= 1) {
            int up = __shfl_up_sync(0xffffffffu, tot, d);
            if (lane >= d) tot += up;
        }
        int excl = tot - pfx;
#pragma unroll
        for (int i = 0; i < 4; ++i) {
            int u = 4 * lane + i;
            if (u >= 1) cc_sh[u] = 2 + excl + c[i];
        }
    }
    __syncwarp();

    bool skipb[5];
#pragma unroll
    for (int i = 0; i < 5; ++i) {
        int s = sB + i;
        skipb[i] = (i < NS) && (s & 1) && (s >= 3) &&
                   (tgt_sh[(s - 1) >> 1] != tgt_sh[(s - 3) >> 1]);
    }

    const int cO1 = 2 * lane + 1;
    const int cO2 = 2 * lane + 2;

    float np[5];
#pragma unroll
    for (int i = 0; i < 5; ++i) np[i] = (sB + i < 2) ? 0.f : NEG_BIG;

    while (flag[0] == 0) {}
    fence_cluster();
    float gE = G_sh[0][0], gO1 = G_sh[0][cO1], gO2 = G_sh[0][cO2];

    for (int t = 1; t < T_; ++t) {
        while (flag[t] == 0) {}
        fence_cluster();
        const float aE = G_sh[t][0], aO1 = G_sh[t][cO1], aO2 = G_sh[t][cO2];
        const int cc_t = cc_sh[t];

        // E-domain step: E = max(ex2(np+g), 2^-126)  [== reference's TINY clamp]
        float e[5];
        e[0] = fmaxf(ex2f(np[0] + gE),  MINF);
        e[1] = fmaxf(ex2f(np[1] + gO1), MINF);
        e[2] = fmaxf(ex2f(np[2] + gE),  MINF);
        e[3] = fmaxf(ex2f(np[3] + gO2), MINF);
        e[4] = fmaxf(ex2f(np[4] + gE),  MINF);
#pragma unroll
        for (int i = 0; i < 5; ++i)
            if (sB + i > cc_t) e[i] = MINF;

        const float em1 = __shfl_up_sync(0xffffffffu, e[3], 1);
        const float em2 = __shfl_up_sync(0xffffffffu, e[2], 1);

        np[0] = (lane == 0) ? lg2f(e[0])
                            : lg2f(e[0] + em1 + (skipb[0] ? em2 : 0.f));
        np[1] = lg2f(e[1] + e[0] + (skipb[1] ? em1 : 0.f));
#pragma unroll
        for (int i = 2; i < 5; ++i)
            np[i] = lg2f(e[i] + e[i - 1] + (skipb[i] ? e[i - 2] : 0.f));

        gE = aE; gO1 = aO1; gO2 = aO2;
    }

    // final: res2[s] = np2[s] + G2[127][s]
    res_sh[sB + 0] = np[0] + gE;
    res_sh[sB + 1] = np[1] + gO1;
    res_sh[sB + 2] = np[2] + gE;
    res_sh[sB + 3] = np[3] + gO2;
    if (lane == 31) res_sh[128] = np[4] + gE;
    __syncwarp();

    if (lane == 0) {
        const int   L = 2 * tlen[n] + 1;
        const float x = res_sh[L - 1], y = res_sh[L - 2];
        const float mx = fmaxf(x, y);
        const float l2 = mx + lg2f(ex2f(x - mx) + ex2f(y - mx));
        out[n] = -((LN2 * l2) / (float)tlen[n]);
    }
}

} // anonymous namespace

extern "C" void kernel_launch(void* const* d_in, const int* /*in_sizes*/, int /*n_in*/,
                              void* d_out, int /*out_size*/) {
    const float* mask     = (const float*)d_in[0];
    const float* classify = (const float*)d_in[1];
    const int*   targets  = (const int*)d_in[2];
    // d_in[3] = input_lengths (always T, unused)
    const int*   tlen     = (const int*)d_in[4];

    fused_kernel<<<2 * N_, 512>>>(mask, classify, targets, tlen, (float*)d_out);
}

// round 8
// speedup vs baseline: 1.8758x; 1.5444x over previous
#include <cuda_runtime.h>
#include <cstdint>

namespace {

constexpr int T_ = 128, H_ = 16, N_ = 64, C_ = 256, S_ = 129;
constexpr int NC_ = N_ * C_;

constexpr float L2E     = 1.4426950408889634f;
constexpr float LN2     = 0.6931471805599453f;
constexpr float MINF    = 1.17549435e-38f;     // 2^-126 == FLT_MIN == TINY
constexpr float NEG_BIG = -1e30f;

__device__ __forceinline__ float ex2f(float x) { float y; asm("ex2.approx.f32 %0, %1;" : "=f"(y) : "f"(x)); return y; }
__device__ __forceinline__ float lg2f(float x) { float y; asm("lg2.approx.f32 %0, %1;" : "=f"(y) : "f"(x)); return y; }

__device__ __forceinline__ uint32_t smem_u32(const void* p) {
    uint32_t a;
    asm("{ .reg .u64 t; cvta.to.shared.u64 t, %1; cvt.u32.u64 %0, t; }" : "=r"(a) : "l"(p));
    return a;
}
__device__ __forceinline__ uint32_t mapa_rank0(uint32_t local) {
    uint32_t r;
    asm("mapa.shared::cluster.u32 %0, %1, 0;" : "=r"(r) : "r"(local));
    return r;
}
__device__ __forceinline__ void st_cl_f32(uint32_t a, float v) {
    asm volatile("st.shared::cluster.f32 [%0], %1;" :: "r"(a), "f"(v));
}
__device__ __forceinline__ void mbar_init(uint32_t a, unsigned cnt) {
    asm volatile("mbarrier.init.shared.b64 [%0], %1;" :: "r"(a), "r"(cnt) : "memory");
}
// per-lane release-arrive on (possibly remote) rank0 barrier
__device__ __forceinline__ void mbar_arrive_cluster(uint32_t mapped) {
    asm volatile("mbarrier.arrive.release.cluster.shared::cluster.b64 _, [%0];"
                 :: "r"(mapped) : "memory");
}
// acquire sleep-wait, parity 0 (single-use barriers)
__device__ __forceinline__ void mbar_wait0(uint32_t a) {
    uint32_t done;
    asm volatile(
        "{\n\t.reg .pred p;\n\t"
        "mbarrier.try_wait.parity.acquire.cta.shared::cta.b64 p, [%1], 0;\n\t"
        "selp.b32 %0, 1, 0, p;\n\t}"
        : "=r"(done) : "r"(a) : "memory");
    if (!done) {
        asm volatile(
            "{\n\t.reg .pred P1;\n\t"
            "WL_%=:\n\t"
            "mbarrier.try_wait.parity.acquire.cta.shared::cta.b64 P1, [%0], 0, 0x989680;\n\t"
            "@P1 bra.uni WD_%=;\n\t"
            "bra.uni WL_%=;\n\t"
            "WD_%=:\n\t}"
            :: "r"(a) : "memory");
    }
}
__device__ __forceinline__ void cluster_sync() {
    asm volatile("barrier.cluster.arrive.aligned;" ::: "memory");
    asm volatile("barrier.cluster.wait.aligned;" ::: "memory");
}
__device__ __forceinline__ uint32_t ctarank() {
    uint32_t r; asm("mov.u32 %0, %%cluster_ctarank;" : "=r"(r)); return r;
}

// 2-CTA cluster per batch item n. Rank0: 15 producer warps + consumer warp 15.
// Rank1: 16 producer warps. Producers write G2 rows (log2 domain, 65 deduped
// columns) into rank0's smem via DSMEM; each lane release-arrives on the row's
// mbarrier. Consumer acquire-waits per row, runs the serial CTC recurrence.
__global__ __launch_bounds__(512, 1) __cluster_dims__(2, 1, 1)
void fused_kernel(
    const float* __restrict__ mask,      // [T,H,N]
    const float* __restrict__ classify,  // [T,H,N,C]
    const int*   __restrict__ targets,   // [N,64]
    const int*   __restrict__ tlen,      // [N]
    float* __restrict__ out)             // [N]
{
    __shared__ float    G_sh[T_][68];
    __shared__ uint64_t mbar[T_];
    __shared__ int      tgt_sh[64];
    __shared__ int      cc_sh[T_];
    __shared__ float    res_sh[S_];

    const int n    = blockIdx.x >> 1;
    const int rank = (int)ctarank();
    const int tid  = threadIdx.x;
    const int w    = tid >> 5;
    const int lane = tid & 31;

    if (rank == 0 && tid < T_) mbar_init(smem_u32(&mbar[tid]), 32);
    if (tid < 64) tgt_sh[tid] = targets[n * 64 + tid];
    __syncthreads();
    cluster_sync();                 // barriers live before any producer arrive

    const bool isProd = (rank == 1) || (w < 15);

    if (isProd) {
        // ======================= producer warp =======================
        const int pid  = (rank == 0) ? w : (15 + w);           // 0..30
        const int col1 = (lane == 0) ? 0 : tgt_sh[lane - 1];   // cols 0..31
        const int col2 = tgt_sh[31 + lane];                    // cols 32..63
        const int col3 = tgt_sh[63];                           // col 64
        const size_t b1 = (size_t)n * C_ + col1;
        const size_t b2 = (size_t)n * C_ + col2;
        const size_t b3 = (size_t)n * C_ + col3;
        const bool   l31 = (lane == 31);

        for (int t = pid; t < T_; t += 31) {
            const float* base = classify + (size_t)t * H_ * NC_;
            const float  m = (lane < 16) ? __ldg(&mask[((size_t)t * H_ + lane) * N_ + n]) : 0.f;

            float v1[H_], v2[H_], v3[H_];
#pragma unroll
            for (int h = 0; h < H_; ++h) {
                const size_t ho = (size_t)h * NC_;
                v1[h] = __ldg(base + ho + b1);
                v2[h] = __ldg(base + ho + b2);
            }
            if (l31) {
#pragma unroll
                for (int h = 0; h < H_; ++h) v3[h] = __ldg(base + (size_t)h * NC_ + b3);
            }

            float s1 = 0.f, s2 = 0.f, s3 = 0.f;
#pragma unroll
            for (int h = 0; h < H_; ++h) {
                const float mh = __shfl_sync(0xffffffffu, m, h) * L2E;
                s1 += ex2f(__fmaf_rn(v1[h], L2E, mh));
                s2 += ex2f(__fmaf_rn(v2[h], L2E, mh));
                if (l31) s3 += ex2f(__fmaf_rn(v3[h], L2E, mh));
            }

            // write row t into rank0's smem, then per-lane release-arrive
            const uint32_t r0 = mapa_rank0(smem_u32(&G_sh[t][0]));
            st_cl_f32(r0 + 4u * lane,        lg2f(s1));
            st_cl_f32(r0 + 4u * (32 + lane), lg2f(s2));
            if (l31) st_cl_f32(r0 + 4u * 64, lg2f(s3));
            mbar_arrive_cluster(mapa_rank0(smem_u32(&mbar[t])));
        }
        return;
    }

    // =================== consumer warp (rank0, w == 15) ===================
    const int NS = (lane == 31) ? 5 : 4;
    const int sB = 4 * lane;

    // cc prefix scan (reachability frontier)
    {
        int c[4], pfx = 0;
#pragma unroll
        for (int i = 0; i < 4; ++i) {
            int u = 4 * lane + i, v = 0;
            if (u >= 2) {
                int sk = 0;
                if ((u & 1) && u >= 3) sk = (tgt_sh[(u - 1) >> 1] != tgt_sh[(u - 3) >> 1]);
                v = sk + 1;
            }
            pfx += v; c[i] = pfx;
        }
        int tot = pfx;
#pragma unroll
        for (int d = 1; d < 32; d <<= 1) {
            int up = __shfl_up_sync(0xffffffffu, tot, d);
            if (lane >= d) tot += up;
        }
        int excl = tot - pfx;
#pragma unroll
        for (int i = 0; i < 4; ++i) {
            int u = 4 * lane + i;
            if (u >= 1) cc_sh[u] = 2 + excl + c[i];
        }
    }
    __syncwarp();

    bool skipb[5];
#pragma unroll
    for (int i = 0; i < 5; ++i) {
        int s = sB + i;
        skipb[i] = (i < NS) && (s & 1) && (s >= 3) &&
                   (tgt_sh[(s - 1) >> 1] != tgt_sh[(s - 3) >> 1]);
    }

    const int cO1 = 2 * lane + 1;
    const int cO2 = 2 * lane + 2;

    float np[5];
#pragma unroll
    for (int i = 0; i < 5; ++i) np[i] = (sB + i < 2) ? 0.f : NEG_BIG;

    mbar_wait0(smem_u32(&mbar[0]));
    float gE = G_sh[0][0], gO1 = G_sh[0][cO1], gO2 = G_sh[0][cO2];

    for (int t = 1; t < T_; ++t) {
        mbar_wait0(smem_u32(&mbar[t]));
        const float aE = G_sh[t][0], aO1 = G_sh[t][cO1], aO2 = G_sh[t][cO2];
        const int cc_t = cc_sh[t];

        // E-domain step: E = max(ex2(np+g), 2^-126)  [== reference's TINY clamp]
        float e[5];
        e[0] = fmaxf(ex2f(np[0] + gE),  MINF);
        e[1] = fmaxf(ex2f(np[1] + gO1), MINF);
        e[2] = fmaxf(ex2f(np[2] + gE),  MINF);
        e[3] = fmaxf(ex2f(np[3] + gO2), MINF);
        e[4] = fmaxf(ex2f(np[4] + gE),  MINF);
#pragma unroll
        for (int i = 0; i < 5; ++i)
            if (sB + i > cc_t) e[i] = MINF;

        const float em1 = __shfl_up_sync(0xffffffffu, e[3], 1);
        const float em2 = __shfl_up_sync(0xffffffffu, e[2], 1);

        np[0] = (lane == 0) ? lg2f(e[0])
                            : lg2f(e[0] + em1 + (skipb[0] ? em2 : 0.f));
        np[1] = lg2f(e[1] + e[0] + (skipb[1] ? em1 : 0.f));
#pragma unroll
        for (int i = 2; i < 5; ++i)
            np[i] = lg2f(e[i] + e[i - 1] + (skipb[i] ? e[i - 2] : 0.f));

        gE = aE; gO1 = aO1; gO2 = aO2;
    }

    // final: res2[s] = np2[s] + G2[127][s]
    res_sh[sB + 0] = np[0] + gE;
    res_sh[sB + 1] = np[1] + gO1;
    res_sh[sB + 2] = np[2] + gE;
    res_sh[sB + 3] = np[3] + gO2;
    if (lane == 31) res_sh[128] = np[4] + gE;
    __syncwarp();

    if (lane == 0) {
        const int   L = 2 * tlen[n] + 1;
        const float x = res_sh[L - 1], y = res_sh[L - 2];
        const float mx = fmaxf(x, y);
        const float l2 = mx + lg2f(ex2f(x - mx) + ex2f(y - mx));
        out[n] = -((LN2 * l2) / (float)tlen[n]);
    }
}

} // anonymous namespace

extern "C" void kernel_launch(void* const* d_in, const int* /*in_sizes*/, int /*n_in*/,
                              void* d_out, int /*out_size*/) {
    const float* mask     = (const float*)d_in[0];
    const float* classify = (const float*)d_in[1];
    const int*   targets  = (const int*)d_in[2];
    // d_in[3] = input_lengths (always T, unused)
    const int*   tlen     = (const int*)d_in[4];

    fused_kernel<<<2 * N_, 512>>>(mask, classify, targets, tlen, (float*)d_out);
}

// round 9
// speedup vs baseline: 1.8880x; 1.0065x over previous
#include <cuda_runtime.h>
#include <cstdint>

namespace {

constexpr int T_ = 128, H_ = 16, N_ = 64, C_ = 256, S_ = 129;
constexpr int NC_ = N_ * C_;

constexpr float L2E     = 1.4426950408889634f;
constexpr float LN2     = 0.6931471805599453f;
constexpr float MINF    = 1.17549435e-38f;     // 2^-126 == FLT_MIN == TINY
constexpr float NEG_BIG = -1e30f;

__device__ __forceinline__ float ex2f(float x) { float y; asm("ex2.approx.f32 %0, %1;" : "=f"(y) : "f"(x)); return y; }
__device__ __forceinline__ float lg2f(float x) { float y; asm("lg2.approx.f32 %0, %1;" : "=f"(y) : "f"(x)); return y; }

__device__ __forceinline__ uint32_t smem_u32(const void* p) {
    uint32_t a;
    asm("{ .reg .u64 t; cvta.to.shared.u64 t, %1; cvt.u32.u64 %0, t; }" : "=r"(a) : "l"(p));
    return a;
}
__device__ __forceinline__ uint32_t mapa_rank0(uint32_t local) {
    uint32_t r;
    asm("mapa.shared::cluster.u32 %0, %1, 0;" : "=r"(r) : "r"(local));
    return r;
}
__device__ __forceinline__ void st_cl_f32(uint32_t a, float v) {
    asm volatile("st.shared::cluster.f32 [%0], %1;" :: "r"(a), "f"(v));
}
__device__ __forceinline__ void mbar_init(uint32_t a, unsigned cnt) {
    asm volatile("mbarrier.init.shared.b64 [%0], %1;" :: "r"(a), "r"(cnt) : "memory");
}
__device__ __forceinline__ void mbar_arrive_cluster(uint32_t mapped) {
    asm volatile("mbarrier.arrive.release.cluster.shared::cluster.b64 _, [%0];"
                 :: "r"(mapped) : "memory");
}
__device__ __forceinline__ void mbar_wait0(uint32_t a) {
    uint32_t done;
    asm volatile(
        "{\n\t.reg .pred p;\n\t"
        "mbarrier.try_wait.parity.acquire.cta.shared::cta.b64 p, [%1], 0;\n\t"
        "selp.b32 %0, 1, 0, p;\n\t}"
        : "=r"(done) : "r"(a) : "memory");
    if (!done) {
        asm volatile(
            "{\n\t.reg .pred P1;\n\t"
            "WL_%=:\n\t"
            "mbarrier.try_wait.parity.acquire.cta.shared::cta.b64 P1, [%0], 0, 0x989680;\n\t"
            "@P1 bra.uni WD_%=;\n\t"
            "bra.uni WL_%=;\n\t"
            "WD_%=:\n\t}"
            :: "r"(a) : "memory");
    }
}
__device__ __forceinline__ void cluster_sync() {
    asm volatile("barrier.cluster.arrive.aligned;" ::: "memory");
    asm volatile("barrier.cluster.wait.aligned;" ::: "memory");
}
__device__ __forceinline__ uint32_t ctarank() {
    uint32_t r; asm("mov.u32 %0, %%cluster_ctarank;" : "=r"(r)); return r;
}

// 2-CTA cluster per n. Rank0: 15 producer warps + consumer warp 15; rank1: 16
// producer warps. Producers load FULL classify rows coalesced (float4), compute
// ex2 for all 256 columns (lane owns cols {4l..4l+3} U {128+4l..131+4l}),
// accumulate per-column sums over h, then write lg2 of the needed (deduped)
// columns into rank0's G row via a precomputed per-lane table. Per-lane
// release-arrive on the row mbarrier; consumer acquire-waits per row.
__global__ __launch_bounds__(512, 1) __cluster_dims__(2, 1, 1)
void fused_kernel(
    const float* __restrict__ mask,      // [T,H,N]
    const float* __restrict__ classify,  // [T,H,N,C]
    const int*   __restrict__ targets,   // [N,64]
    const int*   __restrict__ tlen,      // [N]
    float* __restrict__ out)             // [N]
{
    __shared__ float    G_sh[T_][68];
    __shared__ uint64_t mbar[T_];
    __shared__ int      tgt_sh[64];
    __shared__ int      cc_sh[T_];
    __shared__ float    res_sh[S_];
    __shared__ uint16_t ent[32][66];   // per-lane (c_idx<<4 | k) entries
    __shared__ int      cnt[32];

    const int n    = blockIdx.x >> 1;
    const int rank = (int)ctarank();
    const int tid  = threadIdx.x;
    const int w    = tid >> 5;
    const int lane = tid & 31;

    if (rank == 0 && tid < T_) mbar_init(smem_u32(&mbar[tid]), 32);
    if (tid < 64) tgt_sh[tid] = targets[n * 64 + tid];
    __syncthreads();

    // build column->lane ownership table (once per CTA)
    if (tid == 0) {
#pragma unroll
        for (int l = 0; l < 32; ++l) cnt[l] = 0;
        for (int c = 0; c < 65; ++c) {
            const int v     = (c == 0) ? 0 : tgt_sh[c - 1];
            const int owner = (v & 127) >> 2;
            const int k     = (v & 3) | ((v >= 128) ? 4 : 0);
            ent[owner][cnt[owner]++] = (uint16_t)((c << 4) | k);
        }
    }
    __syncthreads();
    cluster_sync();                 // barriers + tables live before producing

    const bool isProd = (rank == 1) || (w < 15);

    if (isProd) {
        // ======================= producer warp =======================
        const int pid = (rank == 0) ? w : (15 + w);   // 0..30
        const int cn  = cnt[lane];
        uint16_t  el[8];
#pragma unroll
        for (int i = 0; i < 8; ++i) el[i] = (i < cn) ? ent[lane][i] : 0;
        const bool spill = (cn > 8);                  // rare heavy-dup case

        for (int t = pid; t < T_; t += 31) {
            const float* b0 = classify + ((size_t)t * H_ * N_ + n) * C_;
            const float  m  = (lane < 16) ? __ldg(&mask[((size_t)t * H_ + lane) * N_ + n]) : 0.f;

            // depth-4 register pipeline over h
            float4 A[4], B[4];
#pragma unroll
            for (int j = 0; j < 4; ++j) {
                const float* r = b0 + (size_t)j * NC_;
                A[j] = *reinterpret_cast<const float4*>(r + 4 * lane);
                B[j] = *reinterpret_cast<const float4*>(r + 128 + 4 * lane);
            }

            float acc0 = 0.f, acc1 = 0.f, acc2 = 0.f, acc3 = 0.f;
            float acc4 = 0.f, acc5 = 0.f, acc6 = 0.f, acc7 = 0.f;
#pragma unroll
            for (int h = 0; h < H_; ++h) {
                const int   slot = h & 3;
                const float4 a = A[slot], bb = B[slot];
                if (h + 4 < H_) {
                    const float* r = b0 + (size_t)(h + 4) * NC_;
                    A[slot] = *reinterpret_cast<const float4*>(r + 4 * lane);
                    B[slot] = *reinterpret_cast<const float4*>(r + 128 + 4 * lane);
                }
                const float mh = __shfl_sync(0xffffffffu, m, h) * L2E;
                acc0 += ex2f(__fmaf_rn(a.x,  L2E, mh));
                acc1 += ex2f(__fmaf_rn(a.y,  L2E, mh));
                acc2 += ex2f(__fmaf_rn(a.z,  L2E, mh));
                acc3 += ex2f(__fmaf_rn(a.w,  L2E, mh));
                acc4 += ex2f(__fmaf_rn(bb.x, L2E, mh));
                acc5 += ex2f(__fmaf_rn(bb.y, L2E, mh));
                acc6 += ex2f(__fmaf_rn(bb.z, L2E, mh));
                acc7 += ex2f(__fmaf_rn(bb.w, L2E, mh));
            }

            // write needed columns of row t into rank0's G_sh
            const uint32_t r0 = mapa_rank0(smem_u32(&G_sh[t][0]));
            const int nreg = spill ? 8 : cn;
#pragma unroll
            for (int i = 0; i < 8; ++i) {
                if (i < nreg) {
                    const int u = el[i];
                    const int k = u & 7;
                    float s = (k == 0) ? acc0 : (k == 1) ? acc1 : (k == 2) ? acc2 :
                              (k == 3) ? acc3 : (k == 4) ? acc4 : (k == 5) ? acc5 :
                              (k == 6) ? acc6 : acc7;
                    st_cl_f32(r0 + 4u * (u >> 4), lg2f(s));
                }
            }
            if (spill) {
                for (int i = 8; i < cn; ++i) {
                    const int u = ent[lane][i];
                    const int k = u & 7;
                    float s = (k == 0) ? acc0 : (k == 1) ? acc1 : (k == 2) ? acc2 :
                              (k == 3) ? acc3 : (k == 4) ? acc4 : (k == 5) ? acc5 :
                              (k == 6) ? acc6 : acc7;
                    st_cl_f32(r0 + 4u * (u >> 4), lg2f(s));
                }
            }
            mbar_arrive_cluster(mapa_rank0(smem_u32(&mbar[t])));
        }
        return;
    }

    // =================== consumer warp (rank0, w == 15) ===================
    const int NS = (lane == 31) ? 5 : 4;
    const int sB = 4 * lane;

    // cc prefix scan (reachability frontier)
    {
        int c[4], pfx = 0;
#pragma unroll
        for (int i = 0; i < 4; ++i) {
            int u = 4 * lane + i, v = 0;
            if (u >= 2) {
                int sk = 0;
                if ((u & 1) && u >= 3) sk = (tgt_sh[(u - 1) >> 1] != tgt_sh[(u - 3) >> 1]);
                v = sk + 1;
            }
            pfx += v; c[i] = pfx;
        }
        int tot = pfx;
#pragma unroll
        for (int d = 1; d < 32; d <<= 1) {
            int up = __shfl_up_sync(0xffffffffu, tot, d);
            if (lane >= d) tot += up;
        }
        int excl = tot - pfx;
#pragma unroll
        for (int i = 0; i < 4; ++i) {
            int u = 4 * lane + i;
            if (u >= 1) cc_sh[u] = 2 + excl + c[i];
        }
    }
    __syncwarp();

    bool skipb[5];
#pragma unroll
    for (int i = 0; i < 5; ++i) {
        int s = sB + i;
        skipb[i] = (i < NS) && (s & 1) && (s >= 3) &&
                   (tgt_sh[(s - 1) >> 1] != tgt_sh[(s - 3) >> 1]);
    }

    const int cO1 = 2 * lane + 1;
    const int cO2 = 2 * lane + 2;

    float np[5];
#pragma unroll
    for (int i = 0; i < 5; ++i) np[i] = (sB + i < 2) ? 0.f : NEG_BIG;

    mbar_wait0(smem_u32(&mbar[0]));
    float gE = G_sh[0][0], gO1 = G_sh[0][cO1], gO2 = G_sh[0][cO2];

    for (int t = 1; t < T_; ++t) {
        mbar_wait0(smem_u32(&mbar[t]));
        const float aE = G_sh[t][0], aO1 = G_sh[t][cO1], aO2 = G_sh[t][cO2];
        const int cc_t = cc_sh[t];

        // E-domain step: E = max(ex2(np+g), 2^-126)  [== reference's TINY clamp]
        float e[5];
        e[0] = fmaxf(ex2f(np[0] + gE),  MINF);
        e[1] = fmaxf(ex2f(np[1] + gO1), MINF);
        e[2] = fmaxf(ex2f(np[2] + gE),  MINF);
        e[3] = fmaxf(ex2f(np[3] + gO2), MINF);
        e[4] = fmaxf(ex2f(np[4] + gE),  MINF);
#pragma unroll
        for (int i = 0; i < 5; ++i)
            if (sB + i > cc_t) e[i] = MINF;

        const float em1 = __shfl_up_sync(0xffffffffu, e[3], 1);
        const float em2 = __shfl_up_sync(0xffffffffu, e[2], 1);

        np[0] = (lane == 0) ? lg2f(e[0])
                            : lg2f(e[0] + em1 + (skipb[0] ? em2 : 0.f));
        np[1] = lg2f(e[1] + e[0] + (skipb[1] ? em1 : 0.f));
#pragma unroll
        for (int i = 2; i < 5; ++i)
            np[i] = lg2f(e[i] + e[i - 1] + (skipb[i] ? e[i - 2] : 0.f));

        gE = aE; gO1 = aO1; gO2 = aO2;
    }

    // final: res2[s] = np2[s] + G2[127][s]
    res_sh[sB + 0] = np[0] + gE;
    res_sh[sB + 1] = np[1] + gO1;
    res_sh[sB + 2] = np[2] + gE;
    res_sh[sB + 3] = np[3] + gO2;
    if (lane == 31) res_sh[128] = np[4] + gE;
    __syncwarp();

    if (lane == 0) {
        const int   L = 2 * tlen[n] + 1;
        const float x = res_sh[L - 1], y = res_sh[L - 2];
        const float mx = fmaxf(x, y);
        const float l2 = mx + lg2f(ex2f(x - mx) + ex2f(y - mx));
        out[n] = -((LN2 * l2) / (float)tlen[n]);
    }
}

} // anonymous namespace

extern "C" void kernel_launch(void* const* d_in, const int* /*in_sizes*/, int /*n_in*/,
                              void* d_out, int /*out_size*/) {
    const float* mask     = (const float*)d_in[0];
    const float* classify = (const float*)d_in[1];
    const int*   targets  = (const int*)d_in[2];
    // d_in[3] = input_lengths (always T, unused)
    const int*   tlen     = (const int*)d_in[4];

    fused_kernel<<<2 * N_, 512>>>(mask, classify, targets, tlen, (float*)d_out);
}